// round 1
// baseline (speedup 1.0000x reference)
#include <cuda_runtime.h>
#include <math.h>

// Problem dims
#define NTOK 65536
#define ADIM 32
#define LDIM 256
#define KCB  1024

// Scratch (allocation-free: __device__ globals)
__device__ float  g_bufA[(size_t)NTOK * 1024];
__device__ float  g_bufB[(size_t)NTOK * 1024];
__device__ float  g_ze  [(size_t)NTOK * 256];
__device__ float  g_zq  [(size_t)NTOK * 256];
__device__ float  g_cbn [1024 * 256];
__device__ float  g_cbsq[1024];
__device__ double g_acc[2];   // [0]=recon sum, [1]=vq sum

// ---------- packed f32x2 helpers (sm_100+) ----------
__device__ __forceinline__ unsigned long long f2pack(float lo, float hi) {
    unsigned long long r;
    asm("mov.b64 %0, {%1, %2};" : "=l"(r) : "f"(lo), "f"(hi));
    return r;
}
__device__ __forceinline__ void f2unpack(unsigned long long p, float& lo, float& hi) {
    asm("mov.b64 {%0, %1}, %2;" : "=f"(lo), "=f"(hi) : "l"(p));
}
__device__ __forceinline__ void fma2(unsigned long long& d, unsigned long long a, unsigned long long b) {
    asm("fma.rn.f32x2 %0, %1, %2, %0;" : "+l"(d) : "l"(a), "l"(b));
}

// jax.nn.gelu (approximate=True): 0.5*x*(1+tanh(sqrt(2/pi)*(x+0.044715*x^3)))
__device__ __forceinline__ float gelu_t(float x) {
    float x3 = x * x * x;
    float u  = 0.7978845608028654f * (x + 0.044715f * x3);
    return 0.5f * x * (1.0f + tanhf(u));
}

// ---------- generic SGEMM: C = A[M,K] @ B[K,N] + bias, optional gelu ----------
// BM=128 BN=128 BK=16, 256 threads, 8x8 microtile via packed f32x2 FMA.
// Requires M%128==0, N%128==0, K%16==0 (true for all call sites).
template<bool GELU>
__global__ __launch_bounds__(256, 2)
void sgemm_bias(const float* __restrict__ A, const float* __restrict__ B,
                const float* __restrict__ bias, float* __restrict__ C,
                int M, int N, int K) {
    __shared__ float As[16][128];
    __shared__ float Bs[16][128];
    const int tid   = threadIdx.x;
    const int tx    = tid & 15, ty = tid >> 4;
    const int aRow  = tid >> 2, aCol4 = (tid & 3) << 2;
    const int bRow  = tid >> 5, bCol4 = (tid & 31) << 2;
    const float* Ab = A + (size_t)blockIdx.y * 128 * K;
    const float* Bb = B + (size_t)blockIdx.x * 128;

    unsigned long long acc[8][4];
#pragma unroll
    for (int i = 0; i < 8; i++)
#pragma unroll
        for (int j = 0; j < 4; j++) acc[i][j] = 0ull;

    for (int k0 = 0; k0 < K; k0 += 16) {
#pragma unroll
        for (int h = 0; h < 2; h++) {
            int r = aRow + h * 64;
            float4 va = *(const float4*)(Ab + (size_t)r * K + k0 + aCol4);
            As[aCol4 + 0][r] = va.x; As[aCol4 + 1][r] = va.y;
            As[aCol4 + 2][r] = va.z; As[aCol4 + 3][r] = va.w;
        }
#pragma unroll
        for (int h = 0; h < 2; h++) {
            int r = bRow + h * 8;
            *(float4*)(&Bs[r][bCol4]) = *(const float4*)(Bb + (size_t)(k0 + r) * N + bCol4);
        }
        __syncthreads();
#pragma unroll
        for (int k = 0; k < 16; k++) {
            unsigned long long b2[4];
#pragma unroll
            for (int jp = 0; jp < 4; jp++)
                b2[jp] = *(const unsigned long long*)(&Bs[k][tx * 8 + jp * 2]);
            float4 a0 = *(const float4*)(&As[k][ty * 8]);
            float4 a1 = *(const float4*)(&As[k][ty * 8 + 4]);
            float af[8] = {a0.x, a0.y, a0.z, a0.w, a1.x, a1.y, a1.z, a1.w};
#pragma unroll
            for (int i = 0; i < 8; i++) {
                unsigned long long a2 = f2pack(af[i], af[i]);
#pragma unroll
                for (int jp = 0; jp < 4; jp++) fma2(acc[i][jp], a2, b2[jp]);
            }
        }
        __syncthreads();
    }
    const int row0 = blockIdx.y * 128 + ty * 8;
    const int col0 = blockIdx.x * 128 + tx * 8;
    float bb[8];
#pragma unroll
    for (int j = 0; j < 8; j++) bb[j] = bias[col0 + j];
#pragma unroll
    for (int i = 0; i < 8; i++) {
        float c[8];
#pragma unroll
        for (int jp = 0; jp < 4; jp++) f2unpack(acc[i][jp], c[jp * 2], c[jp * 2 + 1]);
#pragma unroll
        for (int j = 0; j < 8; j++) {
            float x = c[j] + bb[j];
            if (GELU) x = gelu_t(x);
            c[j] = x;
        }
        float* Cp = C + (size_t)(row0 + i) * N + col0;
        *(float4*)(Cp)     = make_float4(c[0], c[1], c[2], c[3]);
        *(float4*)(Cp + 4) = make_float4(c[4], c[5], c[6], c[7]);
    }
}

// ---------- codebook re-normalize + squared norms (one warp per row) ----------
__global__ void prep_cb(const float* __restrict__ cb) {
    int warp = (blockIdx.x * blockDim.x + threadIdx.x) >> 5;
    int lane = threadIdx.x & 31;
    if (warp >= 1024) return;
    const float* x = cb + (size_t)warp * 256;
    float v[8]; float s = 0.f;
#pragma unroll
    for (int i = 0; i < 8; i++) { v[i] = x[lane + i * 32]; s += v[i] * v[i]; }
#pragma unroll
    for (int o = 16; o; o >>= 1) s += __shfl_xor_sync(0xffffffffu, s, o);
    float den = sqrtf(s) + 1e-8f;
    float s2 = 0.f;
#pragma unroll
    for (int i = 0; i < 8; i++) {
        float y = v[i] / den;
        g_cbn[(size_t)warp * 256 + lane + i * 32] = y;
        s2 += y * y;
    }
#pragma unroll
    for (int o = 16; o; o >>= 1) s2 += __shfl_xor_sync(0xffffffffu, s2, o);
    if (lane == 0) g_cbsq[warp] = s2;
}

// ---------- in-place row l2norm, one warp per 256-wide row ----------
__global__ void l2norm_rows(float* __restrict__ X, int rows) {
    int warp = (blockIdx.x * blockDim.x + threadIdx.x) >> 5;
    int lane = threadIdx.x & 31;
    if (warp >= rows) return;
    float* x = X + (size_t)warp * 256;
    float v[8]; float s = 0.f;
#pragma unroll
    for (int i = 0; i < 8; i++) { v[i] = x[lane + i * 32]; s += v[i] * v[i]; }
#pragma unroll
    for (int o = 16; o; o >>= 1) s += __shfl_xor_sync(0xffffffffu, s, o);
    float den = sqrtf(s) + 1e-8f;
#pragma unroll
    for (int i = 0; i < 8; i++) x[lane + i * 32] = v[i] / den;
}

// ---------- fused distance-GEMM + argmin + z_q gather + VQ loss ----------
// One block per 128 z_e rows. Loops 8 code tiles of 128; dist = cb_sq - 2*dot
// (per-row constant ||z_e||^2 dropped: argmin-invariant). Exact first-min
// tie-break to match jnp.argmin.
__global__ __launch_bounds__(256, 2)
void vq_kernel(const float* __restrict__ ZE, float* __restrict__ outIdxF) {
    __shared__ float As[16][128];
    __shared__ float Bs[16][128];
    __shared__ float sval[128][17];
    __shared__ int   sidx[128][17];
    __shared__ int   fidx[128];
    __shared__ double dred[8];
    const int tid  = threadIdx.x;
    const int tx   = tid & 15, ty = tid >> 4;
    const int aRow = tid >> 2, aCol4 = (tid & 3) << 2;
    const float* Ab = ZE + (size_t)blockIdx.x * 128 * 256;

    float bestv = 1e30f; int besti = 0;   // valid for tid<128 (row = tid)

    for (int ct = 0; ct < 8; ct++) {
        const int cbase = ct * 128;
        unsigned long long acc[8][4];
#pragma unroll
        for (int i = 0; i < 8; i++)
#pragma unroll
            for (int j = 0; j < 4; j++) acc[i][j] = 0ull;

        for (int k0 = 0; k0 < 256; k0 += 16) {
#pragma unroll
            for (int h = 0; h < 2; h++) {
                int r = aRow + h * 64;
                float4 va = *(const float4*)(Ab + (size_t)r * 256 + k0 + aCol4);
                As[aCol4 + 0][r] = va.x; As[aCol4 + 1][r] = va.y;
                As[aCol4 + 2][r] = va.z; As[aCol4 + 3][r] = va.w;
                float4 vb = *(const float4*)(g_cbn + (size_t)(cbase + r) * 256 + k0 + aCol4);
                Bs[aCol4 + 0][r] = vb.x; Bs[aCol4 + 1][r] = vb.y;
                Bs[aCol4 + 2][r] = vb.z; Bs[aCol4 + 3][r] = vb.w;
            }
            __syncthreads();
#pragma unroll
            for (int k = 0; k < 16; k++) {
                unsigned long long b2[4];
#pragma unroll
                for (int jp = 0; jp < 4; jp++)
                    b2[jp] = *(const unsigned long long*)(&Bs[k][tx * 8 + jp * 2]);
                float4 a0 = *(const float4*)(&As[k][ty * 8]);
                float4 a1 = *(const float4*)(&As[k][ty * 8 + 4]);
                float af[8] = {a0.x, a0.y, a0.z, a0.w, a1.x, a1.y, a1.z, a1.w};
#pragma unroll
                for (int i = 0; i < 8; i++) {
                    unsigned long long a2 = f2pack(af[i], af[i]);
#pragma unroll
                    for (int jp = 0; jp < 4; jp++) fma2(acc[i][jp], a2, b2[jp]);
                }
            }
            __syncthreads();
        }
        // per-thread mins (codes ascending within thread; strict < keeps first)
#pragma unroll
        for (int i = 0; i < 8; i++) {
            float bv = 1e30f; int bi = 0;
#pragma unroll
            for (int jp = 0; jp < 4; jp++) {
                float lo, hi; f2unpack(acc[i][jp], lo, hi);
                int c0 = cbase + tx * 8 + jp * 2;
                float v0 = g_cbsq[c0]     - 2.f * lo;
                float v1 = g_cbsq[c0 + 1] - 2.f * hi;
                if (v0 < bv) { bv = v0; bi = c0; }
                if (v1 < bv) { bv = v1; bi = c0 + 1; }
            }
            sval[ty * 8 + i][tx] = bv;
            sidx[ty * 8 + i][tx] = bi;
        }
        __syncthreads();
        if (tid < 128) {
#pragma unroll
            for (int t = 0; t < 16; t++) {
                float v = sval[tid][t]; int ii = sidx[tid][t];
                if (v < bestv || (v == bestv && ii < besti)) { bestv = v; besti = ii; }
            }
        }
        __syncthreads();
    }
    if (tid < 128) {
        fidx[tid] = besti;
        int grow = blockIdx.x * 128 + tid;
        outIdxF[grow] = (float)besti;
    }
    __syncthreads();

    // gather z_q (STE form ze + (zq - ze)) + VQ loss sum((ze - zq)^2)
    double lsum = 0.0;
    size_t gbase = (size_t)blockIdx.x * 128 * 256;
    for (int rr = 0; rr < 128; rr++) {
        int idx  = fidx[rr];
        float ze = ZE[gbase + (size_t)rr * 256 + tid];
        float zq = g_cbn[(size_t)idx * 256 + tid];
        float d  = zq - ze;
        g_zq[gbase + (size_t)rr * 256 + tid] = ze + d;
        lsum += (double)(d * d);
    }
#pragma unroll
    for (int o = 16; o; o >>= 1) lsum += __shfl_xor_sync(0xffffffffu, lsum, o);
    if ((tid & 31) == 0) dred[tid >> 5] = lsum;
    __syncthreads();
    if (tid == 0) {
        double t = 0.0;
        for (int w = 0; w < 8; w++) t += dred[w];
        atomicAdd(&g_acc[1], t);
    }
}

// ---------- final decoder layer [N,512]@[512,32]+b, fused recon loss ----------
__global__ __launch_bounds__(256)
void dec2_recon(const float* __restrict__ X, const float* __restrict__ W,
                const float* __restrict__ b, const float* __restrict__ action,
                const float* __restrict__ dimw, float* __restrict__ outAH) {
    __shared__ float xs[8][512];
    __shared__ double dred[8];
    const int tid = threadIdx.x;
    const size_t rb = (size_t)blockIdx.x * 8;
    for (int e = tid; e < 8 * 512; e += 256)
        xs[e >> 9][e & 511] = X[rb * 512 + e];
    __syncthreads();
    const int r = tid >> 5, j = tid & 31;
    float a0 = 0.f, a1 = 0.f, a2 = 0.f, a3 = 0.f;
#pragma unroll 4
    for (int k = 0; k < 512; k += 4) {
        a0 = fmaf(xs[r][k + 0], W[(k + 0) * 32 + j], a0);
        a1 = fmaf(xs[r][k + 1], W[(k + 1) * 32 + j], a1);
        a2 = fmaf(xs[r][k + 2], W[(k + 2) * 32 + j], a2);
        a3 = fmaf(xs[r][k + 3], W[(k + 3) * 32 + j], a3);
    }
    float ah = (a0 + a1) + (a2 + a3) + b[j];
    size_t gi = (rb + r) * 32 + j;
    outAH[gi] = ah;
    float d = action[gi] - ah;
    double lsum = (double)(d * d * dimw[j]);
#pragma unroll
    for (int o = 16; o; o >>= 1) lsum += __shfl_xor_sync(0xffffffffu, lsum, o);
    if (j == 0) dred[r] = lsum;
    __syncthreads();
    if (tid == 0) {
        double s = 0.0;
        for (int w = 0; w < 8; w++) s += dred[w];
        atomicAdd(&g_acc[0], s);
    }
}

__global__ void zero_acc() { g_acc[0] = 0.0; g_acc[1] = 0.0; }

__global__ void finalize_losses(float* __restrict__ lossOut) {
    double recon = g_acc[0] / (65536.0 * 32.0);
    double vq    = g_acc[1] / (65536.0 * 256.0);
    lossOut[0] = (float)recon;
    lossOut[1] = (float)vq;   // codebook_loss
    lossOut[2] = (float)vq;   // commit_loss (numerically identical)
}

extern "C" void kernel_launch(void* const* d_in, const int* in_sizes, int n_in,
                              void* d_out, int out_size) {
    const float* action = (const float*)d_in[0];
    const float* dimw   = (const float*)d_in[1];
    const float* ew0 = (const float*)d_in[2];
    const float* eb0 = (const float*)d_in[3];
    const float* ew1 = (const float*)d_in[4];
    const float* eb1 = (const float*)d_in[5];
    const float* ew2 = (const float*)d_in[6];
    const float* eb2 = (const float*)d_in[7];
    const float* dw0 = (const float*)d_in[8];
    const float* db0 = (const float*)d_in[9];
    const float* dw1 = (const float*)d_in[10];
    const float* db1 = (const float*)d_in[11];
    const float* dw2 = (const float*)d_in[12];
    const float* db2 = (const float*)d_in[13];
    const float* cb  = (const float*)d_in[14];
    float* out = (float*)d_out;

    void *pA, *pB, *pZE, *pZQ;
    cudaGetSymbolAddress(&pA,  g_bufA);
    cudaGetSymbolAddress(&pB,  g_bufB);
    cudaGetSymbolAddress(&pZE, g_ze);
    cudaGetSymbolAddress(&pZQ, g_zq);
    float* bufA = (float*)pA;
    float* bufB = (float*)pB;
    float* ze   = (float*)pZE;
    float* zq   = (float*)pZQ;

    // Output layout: action_hat [N*32], code_idx [N] (as float), 3 losses
    const size_t OFF_IDX  = (size_t)NTOK * ADIM;      // 2097152
    const size_t OFF_LOSS = OFF_IDX + NTOK;           // 2162688

    zero_acc<<<1, 1>>>();
    prep_cb<<<128, 256>>>(cb);
    // encoder
    sgemm_bias<true ><<<dim3(4, 512), 256>>>(action, ew0, eb0, bufA, NTOK, 512, 32);
    sgemm_bias<true ><<<dim3(8, 512), 256>>>(bufA,   ew1, eb1, bufB, NTOK, 1024, 512);
    sgemm_bias<false><<<dim3(2, 512), 256>>>(bufB,   ew2, eb2, ze,   NTOK, 256, 1024);
    l2norm_rows<<<8192, 256>>>(ze, NTOK);
    // VQ: argmin + gather + vq loss + code_idx output
    vq_kernel<<<512, 256>>>(ze, out + OFF_IDX);
    // decoder
    sgemm_bias<true ><<<dim3(8, 512), 256>>>(zq,   dw0, db0, bufA, NTOK, 1024, 256);
    sgemm_bias<true ><<<dim3(4, 512), 256>>>(bufA, dw1, db1, bufB, NTOK, 512, 1024);
    dec2_recon<<<8192, 256>>>(bufB, dw2, db2, action, dimw, out);
    finalize_losses<<<1, 1>>>(out + OFF_LOSS);
}

// round 2
// speedup vs baseline: 1.2025x; 1.2025x over previous
#include <cuda_runtime.h>
#include <math.h>

// Problem dims
#define NTOK 65536
#define ADIM 32
#define LDIM 256
#define KCB  1024

// Scratch (allocation-free: __device__ globals)
__device__ float  g_bufA[(size_t)NTOK * 1024];
__device__ float  g_bufB[(size_t)NTOK * 1024];
__device__ float  g_ze  [(size_t)NTOK * 256];
__device__ float  g_zq  [(size_t)NTOK * 256];
__device__ float  g_cbn [1024 * 256];
__device__ float  g_cbsq[1024];
__device__ double g_acc[2];   // [0]=recon sum, [1]=vq sum

typedef unsigned long long ull;

// ---------- packed f32x2 helpers (sm_100+) ----------
__device__ __forceinline__ ull f2pack(float lo, float hi) {
    ull r;
    asm("mov.b64 %0, {%1, %2};" : "=l"(r) : "f"(lo), "f"(hi));
    return r;
}
__device__ __forceinline__ void f2unpack(ull p, float& lo, float& hi) {
    asm("mov.b64 {%0, %1}, %2;" : "=f"(lo), "=f"(hi) : "l"(p));
}
__device__ __forceinline__ void fma2(ull& d, ull a, ull b) {
    asm("fma.rn.f32x2 %0, %1, %2, %0;" : "+l"(d) : "l"(a), "l"(b));
}

// jax.nn.gelu (approximate=True)
__device__ __forceinline__ float gelu_t(float x) {
    float x3 = x * x * x;
    float u  = 0.7978845608028654f * (x + 0.044715f * x3);
    return 0.5f * x * (1.0f + tanhf(u));
}

#define SPAD 132   // padded smem row (floats); 132*4B = 16B-aligned rows

// ---------- generic SGEMM: C = A[M,K] @ B[K,N] + bias, optional gelu ----------
// BM=BN=128, BK=16, 256 threads, split 4+4 microtile, f32x2 FMA,
// double-buffered smem with register prefetch. Requires K%16==0.
template<bool GELU>
__global__ __launch_bounds__(256, 2)
void sgemm_bias(const float* __restrict__ A, const float* __restrict__ B,
                const float* __restrict__ bias, float* __restrict__ C,
                int M, int N, int K) {
    __shared__ float As[2][16][SPAD];
    __shared__ float Bs[2][16][SPAD];
    const int tid   = threadIdx.x;
    const int tx    = tid & 15, ty = tid >> 4;
    const int aRow  = tid >> 2, aCol4 = (tid & 3) << 2;
    const int bRow  = tid >> 5, bCol4 = (tid & 31) << 2;
    const float* Ab = A + (size_t)blockIdx.y * 128 * K;
    const float* Bb = B + (size_t)blockIdx.x * 128;

    ull acc[8][4];
#pragma unroll
    for (int i = 0; i < 8; i++)
#pragma unroll
        for (int j = 0; j < 4; j++) acc[i][j] = 0ull;

    const int T = K >> 4;
    float4 pa0, pa1, pb0, pb1;

    // prefetch tile 0
    pa0 = *(const float4*)(Ab + (size_t)aRow        * K + aCol4);
    pa1 = *(const float4*)(Ab + (size_t)(aRow + 64) * K + aCol4);
    pb0 = *(const float4*)(Bb + (size_t)bRow       * N + bCol4);
    pb1 = *(const float4*)(Bb + (size_t)(bRow + 8) * N + bCol4);
    {
        float* a0p = &As[0][aCol4][aRow];
        a0p[0 * SPAD] = pa0.x; a0p[1 * SPAD] = pa0.y; a0p[2 * SPAD] = pa0.z; a0p[3 * SPAD] = pa0.w;
        float* a1p = &As[0][aCol4][aRow + 64];
        a1p[0 * SPAD] = pa1.x; a1p[1 * SPAD] = pa1.y; a1p[2 * SPAD] = pa1.z; a1p[3 * SPAD] = pa1.w;
        *(float4*)(&Bs[0][bRow][bCol4])     = pb0;
        *(float4*)(&Bs[0][bRow + 8][bCol4]) = pb1;
    }
    __syncthreads();

    for (int t = 0; t < T; t++) {
        const int cur = t & 1;
        if (t + 1 < T) {
            const int k0 = (t + 1) << 4;
            pa0 = *(const float4*)(Ab + (size_t)aRow        * K + k0 + aCol4);
            pa1 = *(const float4*)(Ab + (size_t)(aRow + 64) * K + k0 + aCol4);
            pb0 = *(const float4*)(Bb + (size_t)(k0 + bRow)     * N + bCol4);
            pb1 = *(const float4*)(Bb + (size_t)(k0 + bRow + 8) * N + bCol4);
        }
#pragma unroll
        for (int k = 0; k < 16; k++) {
            float4 a0 = *(const float4*)(&As[cur][k][ty * 4]);
            float4 a1 = *(const float4*)(&As[cur][k][ty * 4 + 64]);
            ulonglong2 b01 = *(const ulonglong2*)(&Bs[cur][k][tx * 4]);
            ulonglong2 b23 = *(const ulonglong2*)(&Bs[cur][k][tx * 4 + 64]);
            ull bb2[4] = {b01.x, b01.y, b23.x, b23.y};
            float af[8] = {a0.x, a0.y, a0.z, a0.w, a1.x, a1.y, a1.z, a1.w};
#pragma unroll
            for (int i = 0; i < 8; i++) {
                ull a2 = f2pack(af[i], af[i]);
#pragma unroll
                for (int jp = 0; jp < 4; jp++) fma2(acc[i][jp], a2, bb2[jp]);
            }
        }
        if (t + 1 < T) {
            const int nxt = cur ^ 1;
            float* a0p = &As[nxt][aCol4][aRow];
            a0p[0 * SPAD] = pa0.x; a0p[1 * SPAD] = pa0.y; a0p[2 * SPAD] = pa0.z; a0p[3 * SPAD] = pa0.w;
            float* a1p = &As[nxt][aCol4][aRow + 64];
            a1p[0 * SPAD] = pa1.x; a1p[1 * SPAD] = pa1.y; a1p[2 * SPAD] = pa1.z; a1p[3 * SPAD] = pa1.w;
            *(float4*)(&Bs[nxt][bRow][bCol4])     = pb0;
            *(float4*)(&Bs[nxt][bRow + 8][bCol4]) = pb1;
        }
        __syncthreads();
    }

    const int row0 = blockIdx.y * 128;
    const int c0g  = blockIdx.x * 128 + tx * 4;
    float bl[4], bh[4];
#pragma unroll
    for (int j = 0; j < 4; j++) { bl[j] = bias[c0g + j]; bh[j] = bias[c0g + 64 + j]; }
#pragma unroll
    for (int i = 0; i < 8; i++) {
        const int row = row0 + ((i < 4) ? (ty * 4 + i) : (64 + ty * 4 + i - 4));
        float c[8];
#pragma unroll
        for (int jp = 0; jp < 4; jp++) f2unpack(acc[i][jp], c[jp * 2], c[jp * 2 + 1]);
#pragma unroll
        for (int j = 0; j < 4; j++) {
            float x0 = c[j]     + bl[j];
            float x1 = c[4 + j] + bh[j];
            if (GELU) { x0 = gelu_t(x0); x1 = gelu_t(x1); }
            c[j] = x0; c[4 + j] = x1;
        }
        float* Cp = C + (size_t)row * N + c0g;
        *(float4*)(Cp)      = make_float4(c[0], c[1], c[2], c[3]);
        *(float4*)(Cp + 64) = make_float4(c[4], c[5], c[6], c[7]);
    }
}

// ---------- codebook re-normalize + squared norms (one warp per row) ----------
__global__ void prep_cb(const float* __restrict__ cb) {
    int warp = (blockIdx.x * blockDim.x + threadIdx.x) >> 5;
    int lane = threadIdx.x & 31;
    if (warp >= 1024) return;
    const float* x = cb + (size_t)warp * 256;
    float v[8]; float s = 0.f;
#pragma unroll
    for (int i = 0; i < 8; i++) { v[i] = x[lane + i * 32]; s += v[i] * v[i]; }
#pragma unroll
    for (int o = 16; o; o >>= 1) s += __shfl_xor_sync(0xffffffffu, s, o);
    float den = sqrtf(s) + 1e-8f;
    float s2 = 0.f;
#pragma unroll
    for (int i = 0; i < 8; i++) {
        float y = v[i] / den;
        g_cbn[(size_t)warp * 256 + lane + i * 32] = y;
        s2 += y * y;
    }
#pragma unroll
    for (int o = 16; o; o >>= 1) s2 += __shfl_xor_sync(0xffffffffu, s2, o);
    if (lane == 0) g_cbsq[warp] = s2;
}

// ---------- in-place row l2norm, one warp per 256-wide row ----------
__global__ void l2norm_rows(float* __restrict__ X, int rows) {
    int warp = (blockIdx.x * blockDim.x + threadIdx.x) >> 5;
    int lane = threadIdx.x & 31;
    if (warp >= rows) return;
    float* x = X + (size_t)warp * 256;
    float v[8]; float s = 0.f;
#pragma unroll
    for (int i = 0; i < 8; i++) { v[i] = x[lane + i * 32]; s += v[i] * v[i]; }
#pragma unroll
    for (int o = 16; o; o >>= 1) s += __shfl_xor_sync(0xffffffffu, s, o);
    float den = sqrtf(s) + 1e-8f;
#pragma unroll
    for (int i = 0; i < 8; i++) x[lane + i * 32] = v[i] / den;
}

// ---------- fused distance-GEMM + argmin + z_q gather + VQ loss ----------
// One block per 128 z_e rows; 8 code tiles of 128. dist = cb_sq - 2*dot
// (row-constant ||z_e||^2 dropped). Packed (dist,idx) uint64 min gives
// exact first-min tie-break (matches jnp.argmin).
__global__ __launch_bounds__(256, 2)
void vq_kernel(const float* __restrict__ ZE, float* __restrict__ outIdxF) {
    __shared__ float As[2][16][SPAD];
    __shared__ float Bs[2][16][SPAD];
    __shared__ float scb[1024];
    __shared__ ull   bestp[128];
    __shared__ double dred[8];
    const int tid  = threadIdx.x;
    const int tx   = tid & 15, ty = tid >> 4;
    const int aRow = tid >> 2, aCol4 = (tid & 3) << 2;
    const float* Ab = ZE + (size_t)blockIdx.x * 128 * 256;

    // cbsq -> smem; init bests
    for (int e = tid; e < 1024; e += 256) scb[e] = g_cbsq[e];
    if (tid < 128) bestp[tid] = ~0ull;

    for (int ct = 0; ct < 8; ct++) {
        const int cbase = ct * 128;
        const float* Bb = g_cbn + (size_t)cbase * 256;
        ull acc[8][4];
#pragma unroll
        for (int i = 0; i < 8; i++)
#pragma unroll
            for (int j = 0; j < 4; j++) acc[i][j] = 0ull;

        float4 pa0, pa1, pb0, pb1;
        pa0 = *(const float4*)(Ab + (size_t)aRow        * 256 + aCol4);
        pa1 = *(const float4*)(Ab + (size_t)(aRow + 64) * 256 + aCol4);
        pb0 = *(const float4*)(Bb + (size_t)aRow        * 256 + aCol4);
        pb1 = *(const float4*)(Bb + (size_t)(aRow + 64) * 256 + aCol4);
        {   // tile 0 (both As and Bs stored transposed: [k][row/code])
            float* a0p = &As[0][aCol4][aRow];
            a0p[0 * SPAD] = pa0.x; a0p[1 * SPAD] = pa0.y; a0p[2 * SPAD] = pa0.z; a0p[3 * SPAD] = pa0.w;
            float* a1p = &As[0][aCol4][aRow + 64];
            a1p[0 * SPAD] = pa1.x; a1p[1 * SPAD] = pa1.y; a1p[2 * SPAD] = pa1.z; a1p[3 * SPAD] = pa1.w;
            float* b0p = &Bs[0][aCol4][aRow];
            b0p[0 * SPAD] = pb0.x; b0p[1 * SPAD] = pb0.y; b0p[2 * SPAD] = pb0.z; b0p[3 * SPAD] = pb0.w;
            float* b1p = &Bs[0][aCol4][aRow + 64];
            b1p[0 * SPAD] = pb1.x; b1p[1 * SPAD] = pb1.y; b1p[2 * SPAD] = pb1.z; b1p[3 * SPAD] = pb1.w;
        }
        __syncthreads();

        for (int t = 0; t < 16; t++) {
            const int cur = t & 1;
            if (t + 1 < 16) {
                const int k0 = (t + 1) << 4;
                pa0 = *(const float4*)(Ab + (size_t)aRow        * 256 + k0 + aCol4);
                pa1 = *(const float4*)(Ab + (size_t)(aRow + 64) * 256 + k0 + aCol4);
                pb0 = *(const float4*)(Bb + (size_t)aRow        * 256 + k0 + aCol4);
                pb1 = *(const float4*)(Bb + (size_t)(aRow + 64) * 256 + k0 + aCol4);
            }
#pragma unroll
            for (int k = 0; k < 16; k++) {
                float4 a0 = *(const float4*)(&As[cur][k][ty * 4]);
                float4 a1 = *(const float4*)(&As[cur][k][ty * 4 + 64]);
                ulonglong2 b01 = *(const ulonglong2*)(&Bs[cur][k][tx * 4]);
                ulonglong2 b23 = *(const ulonglong2*)(&Bs[cur][k][tx * 4 + 64]);
                ull bb2[4] = {b01.x, b01.y, b23.x, b23.y};
                float af[8] = {a0.x, a0.y, a0.z, a0.w, a1.x, a1.y, a1.z, a1.w};
#pragma unroll
                for (int i = 0; i < 8; i++) {
                    ull a2 = f2pack(af[i], af[i]);
#pragma unroll
                    for (int jp = 0; jp < 4; jp++) fma2(acc[i][jp], a2, bb2[jp]);
                }
            }
            if (t + 1 < 16) {
                const int nxt = cur ^ 1;
                float* a0p = &As[nxt][aCol4][aRow];
                a0p[0 * SPAD] = pa0.x; a0p[1 * SPAD] = pa0.y; a0p[2 * SPAD] = pa0.z; a0p[3 * SPAD] = pa0.w;
                float* a1p = &As[nxt][aCol4][aRow + 64];
                a1p[0 * SPAD] = pa1.x; a1p[1 * SPAD] = pa1.y; a1p[2 * SPAD] = pa1.z; a1p[3 * SPAD] = pa1.w;
                float* b0p = &Bs[nxt][aCol4][aRow];
                b0p[0 * SPAD] = pb0.x; b0p[1 * SPAD] = pb0.y; b0p[2 * SPAD] = pb0.z; b0p[3 * SPAD] = pb0.w;
                float* b1p = &Bs[nxt][aCol4][aRow + 64];
                b1p[0 * SPAD] = pb1.x; b1p[1 * SPAD] = pb1.y; b1p[2 * SPAD] = pb1.z; b1p[3 * SPAD] = pb1.w;
            }
            __syncthreads();
        }

        // per-thread packed mins over its 8 codes, half-warp reduce over tx
#pragma unroll
        for (int i = 0; i < 8; i++) {
            const int row = (i < 4) ? (ty * 4 + i) : (64 + ty * 4 + i - 4);
            ull pmin = ~0ull;
#pragma unroll
            for (int jp = 0; jp < 4; jp++) {
                float lo, hi; f2unpack(acc[i][jp], lo, hi);
                const int c0 = cbase + tx * 4 + ((jp >> 1) << 6) + ((jp & 1) << 1);
                float v0 = scb[c0]     - 2.f * lo;
                float v1 = scb[c0 + 1] - 2.f * hi;
                ull p0 = ((ull)__float_as_uint(v0 + 8.f) << 32) | (unsigned)c0;
                ull p1 = ((ull)__float_as_uint(v1 + 8.f) << 32) | (unsigned)(c0 + 1);
                pmin = min(pmin, p0); pmin = min(pmin, p1);
            }
#pragma unroll
            for (int off = 8; off; off >>= 1) {
                ull o = __shfl_xor_sync(0xffffffffu, pmin, off);
                pmin = min(pmin, o);
            }
            if (tx == 0) bestp[row] = min(bestp[row], pmin);
        }
        __syncthreads();
    }

    if (tid < 128) {
        int besti = (int)(unsigned)(bestp[tid] & 0xffffffffu);
        outIdxF[blockIdx.x * 128 + tid] = (float)besti;
    }
    __syncthreads();

    // gather z_q (STE form ze + (zq - ze)) + VQ loss sum((ze - zq)^2)
    double lsum = 0.0;
    size_t gbase = (size_t)blockIdx.x * 128 * 256;
    for (int rr = 0; rr < 128; rr++) {
        int idx  = (int)(unsigned)(bestp[rr] & 0xffffffffu);
        float ze = ZE[gbase + (size_t)rr * 256 + tid];
        float zq = g_cbn[(size_t)idx * 256 + tid];
        float d  = zq - ze;
        g_zq[gbase + (size_t)rr * 256 + tid] = ze + d;
        lsum += (double)(d * d);
    }
#pragma unroll
    for (int o = 16; o; o >>= 1) lsum += __shfl_xor_sync(0xffffffffu, lsum, o);
    if ((tid & 31) == 0) dred[tid >> 5] = lsum;
    __syncthreads();
    if (tid == 0) {
        double t = 0.0;
        for (int w = 0; w < 8; w++) t += dred[w];
        atomicAdd(&g_acc[1], t);
    }
}

// ---------- final decoder layer [N,512]@[512,32]+b, fused recon loss ----------
__global__ __launch_bounds__(256)
void dec2_recon(const float* __restrict__ X, const float* __restrict__ W,
                const float* __restrict__ b, const float* __restrict__ action,
                const float* __restrict__ dimw, float* __restrict__ outAH) {
    __shared__ float xs[8][512];
    __shared__ double dred[8];
    const int tid = threadIdx.x;
    const size_t rb = (size_t)blockIdx.x * 8;
    for (int e = tid; e < 8 * 512; e += 256)
        xs[e >> 9][e & 511] = X[rb * 512 + e];
    __syncthreads();
    const int r = tid >> 5, j = tid & 31;
    float a0 = 0.f, a1 = 0.f, a2 = 0.f, a3 = 0.f;
#pragma unroll 4
    for (int k = 0; k < 512; k += 4) {
        a0 = fmaf(xs[r][k + 0], W[(k + 0) * 32 + j], a0);
        a1 = fmaf(xs[r][k + 1], W[(k + 1) * 32 + j], a1);
        a2 = fmaf(xs[r][k + 2], W[(k + 2) * 32 + j], a2);
        a3 = fmaf(xs[r][k + 3], W[(k + 3) * 32 + j], a3);
    }
    float ah = (a0 + a1) + (a2 + a3) + b[j];
    size_t gi = (rb + r) * 32 + j;
    outAH[gi] = ah;
    float d = action[gi] - ah;
    double lsum = (double)(d * d * dimw[j]);
#pragma unroll
    for (int o = 16; o; o >>= 1) lsum += __shfl_xor_sync(0xffffffffu, lsum, o);
    if (j == 0) dred[r] = lsum;
    __syncthreads();
    if (tid == 0) {
        double s = 0.0;
        for (int w = 0; w < 8; w++) s += dred[w];
        atomicAdd(&g_acc[0], s);
    }
}

__global__ void zero_acc() { g_acc[0] = 0.0; g_acc[1] = 0.0; }

__global__ void finalize_losses(float* __restrict__ lossOut) {
    double recon = g_acc[0] / (65536.0 * 32.0);
    double vq    = g_acc[1] / (65536.0 * 256.0);
    lossOut[0] = (float)recon;
    lossOut[1] = (float)vq;   // codebook_loss
    lossOut[2] = (float)vq;   // commit_loss (numerically identical)
}

extern "C" void kernel_launch(void* const* d_in, const int* in_sizes, int n_in,
                              void* d_out, int out_size) {
    const float* action = (const float*)d_in[0];
    const float* dimw   = (const float*)d_in[1];
    const float* ew0 = (const float*)d_in[2];
    const float* eb0 = (const float*)d_in[3];
    const float* ew1 = (const float*)d_in[4];
    const float* eb1 = (const float*)d_in[5];
    const float* ew2 = (const float*)d_in[6];
    const float* eb2 = (const float*)d_in[7];
    const float* dw0 = (const float*)d_in[8];
    const float* db0 = (const float*)d_in[9];
    const float* dw1 = (const float*)d_in[10];
    const float* db1 = (const float*)d_in[11];
    const float* dw2 = (const float*)d_in[12];
    const float* db2 = (const float*)d_in[13];
    const float* cb  = (const float*)d_in[14];
    float* out = (float*)d_out;

    void *pA, *pB, *pZE, *pZQ;
    cudaGetSymbolAddress(&pA,  g_bufA);
    cudaGetSymbolAddress(&pB,  g_bufB);
    cudaGetSymbolAddress(&pZE, g_ze);
    cudaGetSymbolAddress(&pZQ, g_zq);
    float* bufA = (float*)pA;
    float* bufB = (float*)pB;
    float* ze   = (float*)pZE;
    float* zq   = (float*)pZQ;

    // Output layout: action_hat [N*32], code_idx [N] (as float), 3 losses
    const size_t OFF_IDX  = (size_t)NTOK * ADIM;      // 2097152
    const size_t OFF_LOSS = OFF_IDX + NTOK;           // 2162688

    zero_acc<<<1, 1>>>();
    prep_cb<<<128, 256>>>(cb);
    // encoder
    sgemm_bias<true ><<<dim3(4, 512), 256>>>(action, ew0, eb0, bufA, NTOK, 512, 32);
    sgemm_bias<true ><<<dim3(8, 512), 256>>>(bufA,   ew1, eb1, bufB, NTOK, 1024, 512);
    sgemm_bias<false><<<dim3(2, 512), 256>>>(bufB,   ew2, eb2, ze,   NTOK, 256, 1024);
    l2norm_rows<<<8192, 256>>>(ze, NTOK);
    // VQ: argmin + gather + vq loss + code_idx output
    vq_kernel<<<512, 256>>>(ze, out + OFF_IDX);
    // decoder
    sgemm_bias<true ><<<dim3(8, 512), 256>>>(zq,   dw0, db0, bufA, NTOK, 1024, 256);
    sgemm_bias<true ><<<dim3(4, 512), 256>>>(bufA, dw1, db1, bufB, NTOK, 512, 1024);
    dec2_recon<<<8192, 256>>>(bufB, dw2, db2, action, dimw, out);
    finalize_losses<<<1, 1>>>(out + OFF_LOSS);
}

// round 3
// speedup vs baseline: 1.8970x; 1.5776x over previous
#include <cuda_runtime.h>
#include <math.h>

// Problem dims
#define NTOK 65536
#define ADIM 32
#define LDIM 256
#define KCB  1024

// Scratch (allocation-free: __device__ globals)
__device__ float  g_bufA[(size_t)NTOK * 1024];
__device__ float  g_bufB[(size_t)NTOK * 1024];
__device__ float  g_ze  [(size_t)NTOK * 256];
__device__ float  g_cbn [1024 * 256];
__device__ float  g_cbsq[1024];
__device__ float  g_dt0 [1024 * 1024];
__device__ float  g_dt1 [1024 * 512];
__device__ float  g_dt2 [1024 * 32];
__device__ double g_acc[2];   // [0]=recon sum, [1]=vq sum

typedef unsigned long long ull;

// ---------- packed f32x2 helpers (sm_100+) ----------
__device__ __forceinline__ ull f2pack(float lo, float hi) {
    ull r;
    asm("mov.b64 %0, {%1, %2};" : "=l"(r) : "f"(lo), "f"(hi));
    return r;
}
__device__ __forceinline__ void f2unpack(ull p, float& lo, float& hi) {
    asm("mov.b64 {%0, %1}, %2;" : "=f"(lo), "=f"(hi) : "l"(p));
}
__device__ __forceinline__ void fma2(ull& d, ull a, ull b) {
    asm("fma.rn.f32x2 %0, %1, %2, %0;" : "+l"(d) : "l"(a), "l"(b));
}

// jax.nn.gelu (approximate=True)
__device__ __forceinline__ float gelu_t(float x) {
    float x3 = x * x * x;
    float u  = 0.7978845608028654f * (x + 0.044715f * x3);
    return 0.5f * x * (1.0f + tanhf(u));
}

#define SPAD 132   // padded smem row (floats); 132*4B = 16B-aligned rows

// ---------- generic SGEMM: C = A[M,K] @ B[K,N] + bias, optional gelu ----------
// BM=BN=128, BK=16, 256 threads, split 4+4 microtile, f32x2 FMA,
// double-buffered smem with register prefetch. Requires M%128==0, N%128==0, K%16==0.
template<bool GELU>
__global__ __launch_bounds__(256, 2)
void sgemm_bias(const float* __restrict__ A, const float* __restrict__ B,
                const float* __restrict__ bias, float* __restrict__ C,
                int M, int N, int K) {
    __shared__ float As[2][16][SPAD];
    __shared__ float Bs[2][16][SPAD];
    const int tid   = threadIdx.x;
    const int tx    = tid & 15, ty = tid >> 4;
    const int aRow  = tid >> 2, aCol4 = (tid & 3) << 2;
    const int bRow  = tid >> 5, bCol4 = (tid & 31) << 2;
    const float* Ab = A + (size_t)blockIdx.y * 128 * K;
    const float* Bb = B + (size_t)blockIdx.x * 128;

    ull acc[8][4];
#pragma unroll
    for (int i = 0; i < 8; i++)
#pragma unroll
        for (int j = 0; j < 4; j++) acc[i][j] = 0ull;

    const int T = K >> 4;
    float4 pa0, pa1, pb0, pb1;

    // prefetch tile 0
    pa0 = *(const float4*)(Ab + (size_t)aRow        * K + aCol4);
    pa1 = *(const float4*)(Ab + (size_t)(aRow + 64) * K + aCol4);
    pb0 = *(const float4*)(Bb + (size_t)bRow       * N + bCol4);
    pb1 = *(const float4*)(Bb + (size_t)(bRow + 8) * N + bCol4);
    {
        float* a0p = &As[0][aCol4][aRow];
        a0p[0 * SPAD] = pa0.x; a0p[1 * SPAD] = pa0.y; a0p[2 * SPAD] = pa0.z; a0p[3 * SPAD] = pa0.w;
        float* a1p = &As[0][aCol4][aRow + 64];
        a1p[0 * SPAD] = pa1.x; a1p[1 * SPAD] = pa1.y; a1p[2 * SPAD] = pa1.z; a1p[3 * SPAD] = pa1.w;
        *(float4*)(&Bs[0][bRow][bCol4])     = pb0;
        *(float4*)(&Bs[0][bRow + 8][bCol4]) = pb1;
    }
    __syncthreads();

    for (int t = 0; t < T; t++) {
        const int cur = t & 1;
        if (t + 1 < T) {
            const int k0 = (t + 1) << 4;
            pa0 = *(const float4*)(Ab + (size_t)aRow        * K + k0 + aCol4);
            pa1 = *(const float4*)(Ab + (size_t)(aRow + 64) * K + k0 + aCol4);
            pb0 = *(const float4*)(Bb + (size_t)(k0 + bRow)     * N + bCol4);
            pb1 = *(const float4*)(Bb + (size_t)(k0 + bRow + 8) * N + bCol4);
        }
#pragma unroll
        for (int k = 0; k < 16; k++) {
            float4 a0 = *(const float4*)(&As[cur][k][ty * 4]);
            float4 a1 = *(const float4*)(&As[cur][k][ty * 4 + 64]);
            ulonglong2 b01 = *(const ulonglong2*)(&Bs[cur][k][tx * 4]);
            ulonglong2 b23 = *(const ulonglong2*)(&Bs[cur][k][tx * 4 + 64]);
            ull bb2[4] = {b01.x, b01.y, b23.x, b23.y};
            float af[8] = {a0.x, a0.y, a0.z, a0.w, a1.x, a1.y, a1.z, a1.w};
#pragma unroll
            for (int i = 0; i < 8; i++) {
                ull a2 = f2pack(af[i], af[i]);
#pragma unroll
                for (int jp = 0; jp < 4; jp++) fma2(acc[i][jp], a2, bb2[jp]);
            }
        }
        if (t + 1 < T) {
            const int nxt = cur ^ 1;
            float* a0p = &As[nxt][aCol4][aRow];
            a0p[0 * SPAD] = pa0.x; a0p[1 * SPAD] = pa0.y; a0p[2 * SPAD] = pa0.z; a0p[3 * SPAD] = pa0.w;
            float* a1p = &As[nxt][aCol4][aRow + 64];
            a1p[0 * SPAD] = pa1.x; a1p[1 * SPAD] = pa1.y; a1p[2 * SPAD] = pa1.z; a1p[3 * SPAD] = pa1.w;
            *(float4*)(&Bs[nxt][bRow][bCol4])     = pb0;
            *(float4*)(&Bs[nxt][bRow + 8][bCol4]) = pb1;
        }
        __syncthreads();
    }

    const int row0 = blockIdx.y * 128;
    const int c0g  = blockIdx.x * 128 + tx * 4;
    float bl[4], bh[4];
#pragma unroll
    for (int j = 0; j < 4; j++) { bl[j] = bias[c0g + j]; bh[j] = bias[c0g + 64 + j]; }
#pragma unroll
    for (int i = 0; i < 8; i++) {
        const int row = row0 + ((i < 4) ? (ty * 4 + i) : (64 + ty * 4 + i - 4));
        float c[8];
#pragma unroll
        for (int jp = 0; jp < 4; jp++) f2unpack(acc[i][jp], c[jp * 2], c[jp * 2 + 1]);
#pragma unroll
        for (int j = 0; j < 4; j++) {
            float x0 = c[j]     + bl[j];
            float x1 = c[4 + j] + bh[j];
            if (GELU) { x0 = gelu_t(x0); x1 = gelu_t(x1); }
            c[j] = x0; c[4 + j] = x1;
        }
        float* Cp = C + (size_t)row * N + c0g;
        *(float4*)(Cp)      = make_float4(c[0], c[1], c[2], c[3]);
        *(float4*)(Cp + 64) = make_float4(c[4], c[5], c[6], c[7]);
    }
}

// ---------- codebook re-normalize + squared norms (one warp per row) ----------
__global__ void prep_cb(const float* __restrict__ cb) {
    int warp = (blockIdx.x * blockDim.x + threadIdx.x) >> 5;
    int lane = threadIdx.x & 31;
    if (warp >= 1024) return;
    const float* x = cb + (size_t)warp * 256;
    float v[8]; float s = 0.f;
#pragma unroll
    for (int i = 0; i < 8; i++) { v[i] = x[lane + i * 32]; s += v[i] * v[i]; }
#pragma unroll
    for (int o = 16; o; o >>= 1) s += __shfl_xor_sync(0xffffffffu, s, o);
    float den = sqrtf(s) + 1e-8f;
    float s2 = 0.f;
#pragma unroll
    for (int i = 0; i < 8; i++) {
        float y = v[i] / den;
        g_cbn[(size_t)warp * 256 + lane + i * 32] = y;
        s2 += y * y;
    }
#pragma unroll
    for (int o = 16; o; o >>= 1) s2 += __shfl_xor_sync(0xffffffffu, s2, o);
    if (lane == 0) g_cbsq[warp] = s2;
}

// ---------- in-place row l2norm, one warp per 256-wide row ----------
__global__ void l2norm_rows(float* __restrict__ X, int rows) {
    int warp = (blockIdx.x * blockDim.x + threadIdx.x) >> 5;
    int lane = threadIdx.x & 31;
    if (warp >= rows) return;
    float* x = X + (size_t)warp * 256;
    float v[8]; float s = 0.f;
#pragma unroll
    for (int i = 0; i < 8; i++) { v[i] = x[lane + i * 32]; s += v[i] * v[i]; }
#pragma unroll
    for (int o = 16; o; o >>= 1) s += __shfl_xor_sync(0xffffffffu, s, o);
    float den = sqrtf(s) + 1e-8f;
#pragma unroll
    for (int i = 0; i < 8; i++) x[lane + i * 32] = v[i] / den;
}

// ---------- fused distance-GEMM + argmin + VQ loss ----------
// One block per 128 z_e rows; 8 code tiles of 128. dist = cb_sq - 2*dot
// (row-constant ||z_e||^2 dropped). Packed (dist,idx) uint64 min gives
// exact first-min tie-break (matches jnp.argmin).
__global__ __launch_bounds__(256, 2)
void vq_kernel(const float* __restrict__ ZE, float* __restrict__ outIdxF) {
    __shared__ float As[2][16][SPAD];
    __shared__ float Bs[2][16][SPAD];
    __shared__ float scb[1024];
    __shared__ ull   bestp[128];
    __shared__ double dred[8];
    const int tid  = threadIdx.x;
    const int tx   = tid & 15, ty = tid >> 4;
    const int aRow = tid >> 2, aCol4 = (tid & 3) << 2;
    const float* Ab = ZE + (size_t)blockIdx.x * 128 * 256;

    for (int e = tid; e < 1024; e += 256) scb[e] = g_cbsq[e];
    if (tid < 128) bestp[tid] = ~0ull;

    for (int ct = 0; ct < 8; ct++) {
        const int cbase = ct * 128;
        const float* Bb = g_cbn + (size_t)cbase * 256;
        ull acc[8][4];
#pragma unroll
        for (int i = 0; i < 8; i++)
#pragma unroll
            for (int j = 0; j < 4; j++) acc[i][j] = 0ull;

        float4 pa0, pa1, pb0, pb1;
        pa0 = *(const float4*)(Ab + (size_t)aRow        * 256 + aCol4);
        pa1 = *(const float4*)(Ab + (size_t)(aRow + 64) * 256 + aCol4);
        pb0 = *(const float4*)(Bb + (size_t)aRow        * 256 + aCol4);
        pb1 = *(const float4*)(Bb + (size_t)(aRow + 64) * 256 + aCol4);
        {   // tile 0 (both As and Bs stored transposed: [k][row/code])
            float* a0p = &As[0][aCol4][aRow];
            a0p[0 * SPAD] = pa0.x; a0p[1 * SPAD] = pa0.y; a0p[2 * SPAD] = pa0.z; a0p[3 * SPAD] = pa0.w;
            float* a1p = &As[0][aCol4][aRow + 64];
            a1p[0 * SPAD] = pa1.x; a1p[1 * SPAD] = pa1.y; a1p[2 * SPAD] = pa1.z; a1p[3 * SPAD] = pa1.w;
            float* b0p = &Bs[0][aCol4][aRow];
            b0p[0 * SPAD] = pb0.x; b0p[1 * SPAD] = pb0.y; b0p[2 * SPAD] = pb0.z; b0p[3 * SPAD] = pb0.w;
            float* b1p = &Bs[0][aCol4][aRow + 64];
            b1p[0 * SPAD] = pb1.x; b1p[1 * SPAD] = pb1.y; b1p[2 * SPAD] = pb1.z; b1p[3 * SPAD] = pb1.w;
        }
        __syncthreads();

        for (int t = 0; t < 16; t++) {
            const int cur = t & 1;
            if (t + 1 < 16) {
                const int k0 = (t + 1) << 4;
                pa0 = *(const float4*)(Ab + (size_t)aRow        * 256 + k0 + aCol4);
                pa1 = *(const float4*)(Ab + (size_t)(aRow + 64) * 256 + k0 + aCol4);
                pb0 = *(const float4*)(Bb + (size_t)aRow        * 256 + k0 + aCol4);
                pb1 = *(const float4*)(Bb + (size_t)(aRow + 64) * 256 + k0 + aCol4);
            }
#pragma unroll
            for (int k = 0; k < 16; k++) {
                float4 a0 = *(const float4*)(&As[cur][k][ty * 4]);
                float4 a1 = *(const float4*)(&As[cur][k][ty * 4 + 64]);
                ulonglong2 b01 = *(const ulonglong2*)(&Bs[cur][k][tx * 4]);
                ulonglong2 b23 = *(const ulonglong2*)(&Bs[cur][k][tx * 4 + 64]);
                ull bb2[4] = {b01.x, b01.y, b23.x, b23.y};
                float af[8] = {a0.x, a0.y, a0.z, a0.w, a1.x, a1.y, a1.z, a1.w};
#pragma unroll
                for (int i = 0; i < 8; i++) {
                    ull a2 = f2pack(af[i], af[i]);
#pragma unroll
                    for (int jp = 0; jp < 4; jp++) fma2(acc[i][jp], a2, bb2[jp]);
                }
            }
            if (t + 1 < 16) {
                const int nxt = cur ^ 1;
                float* a0p = &As[nxt][aCol4][aRow];
                a0p[0 * SPAD] = pa0.x; a0p[1 * SPAD] = pa0.y; a0p[2 * SPAD] = pa0.z; a0p[3 * SPAD] = pa0.w;
                float* a1p = &As[nxt][aCol4][aRow + 64];
                a1p[0 * SPAD] = pa1.x; a1p[1 * SPAD] = pa1.y; a1p[2 * SPAD] = pa1.z; a1p[3 * SPAD] = pa1.w;
                float* b0p = &Bs[nxt][aCol4][aRow];
                b0p[0 * SPAD] = pb0.x; b0p[1 * SPAD] = pb0.y; b0p[2 * SPAD] = pb0.z; b0p[3 * SPAD] = pb0.w;
                float* b1p = &Bs[nxt][aCol4][aRow + 64];
                b1p[0 * SPAD] = pb1.x; b1p[1 * SPAD] = pb1.y; b1p[2 * SPAD] = pb1.z; b1p[3 * SPAD] = pb1.w;
            }
            __syncthreads();
        }

        // per-thread packed mins over its 8 codes, half-warp reduce over tx
#pragma unroll
        for (int i = 0; i < 8; i++) {
            const int row = (i < 4) ? (ty * 4 + i) : (64 + ty * 4 + i - 4);
            ull pmin = ~0ull;
#pragma unroll
            for (int jp = 0; jp < 4; jp++) {
                float lo, hi; f2unpack(acc[i][jp], lo, hi);
                const int c0 = cbase + tx * 4 + ((jp >> 1) << 6) + ((jp & 1) << 1);
                float v0 = scb[c0]     - 2.f * lo;
                float v1 = scb[c0 + 1] - 2.f * hi;
                ull p0 = ((ull)__float_as_uint(v0 + 8.f) << 32) | (unsigned)c0;
                ull p1 = ((ull)__float_as_uint(v1 + 8.f) << 32) | (unsigned)(c0 + 1);
                pmin = min(pmin, p0); pmin = min(pmin, p1);
            }
#pragma unroll
            for (int off = 8; off; off >>= 1) {
                ull o = __shfl_xor_sync(0xffffffffu, pmin, off);
                pmin = min(pmin, o);
            }
            if (tx == 0) bestp[row] = min(bestp[row], pmin);
        }
        __syncthreads();
    }

    if (tid < 128) {
        int besti = (int)(unsigned)(bestp[tid] & 0xffffffffu);
        outIdxF[blockIdx.x * 128 + tid] = (float)besti;
    }
    __syncthreads();

    // VQ loss sum((ze - zq)^2)  (z_q itself no longer materialized)
    double lsum = 0.0;
    size_t gbase = (size_t)blockIdx.x * 128 * 256;
    for (int rr = 0; rr < 128; rr++) {
        int idx  = (int)(unsigned)(bestp[rr] & 0xffffffffu);
        float ze = ZE[gbase + (size_t)rr * 256 + tid];
        float zq = g_cbn[(size_t)idx * 256 + tid];
        float d  = zq - ze;
        lsum += (double)(d * d);
    }
#pragma unroll
    for (int o = 16; o; o >>= 1) lsum += __shfl_xor_sync(0xffffffffu, lsum, o);
    if ((tid & 31) == 0) dred[tid >> 5] = lsum;
    __syncthreads();
    if (tid == 0) {
        double t = 0.0;
        for (int w = 0; w < 8; w++) t += dred[w];
        atomicAdd(&g_acc[1], t);
    }
}

// ---------- decoder final layer on the 1024-code table: [1024,512]@[512,32]+b ----------
__global__ __launch_bounds__(256)
void dec2_table(const float* __restrict__ X, const float* __restrict__ W,
                const float* __restrict__ b, float* __restrict__ outT) {
    __shared__ float xs[8][512];
    const int tid = threadIdx.x;
    const size_t rb = (size_t)blockIdx.x * 8;
    for (int e = tid; e < 8 * 512; e += 256)
        xs[e >> 9][e & 511] = X[rb * 512 + e];
    __syncthreads();
    const int r = tid >> 5, j = tid & 31;
    float a0 = 0.f, a1 = 0.f, a2 = 0.f, a3 = 0.f;
#pragma unroll 4
    for (int k = 0; k < 512; k += 4) {
        a0 = fmaf(xs[r][k + 0], W[(k + 0) * 32 + j], a0);
        a1 = fmaf(xs[r][k + 1], W[(k + 1) * 32 + j], a1);
        a2 = fmaf(xs[r][k + 2], W[(k + 2) * 32 + j], a2);
        a3 = fmaf(xs[r][k + 3], W[(k + 3) * 32 + j], a3);
    }
    outT[(rb + r) * 32 + j] = (a0 + a1) + (a2 + a3) + b[j];
}

// ---------- gather action_hat from table + recon loss ----------
__global__ __launch_bounds__(256)
void recon_gather(const float* __restrict__ tab, const float* __restrict__ idxF,
                  const float* __restrict__ action, const float* __restrict__ dimw,
                  float* __restrict__ outAH) {
    __shared__ double dred[8];
    const int tid = threadIdx.x;
    const int r = tid >> 5, j = tid & 31;
    const size_t token = (size_t)blockIdx.x * 8 + r;
    const int idx = (int)idxF[token];
    float ah = tab[(size_t)idx * 32 + j];
    size_t gi = token * 32 + j;
    outAH[gi] = ah;
    float d = action[gi] - ah;
    double lsum = (double)(d * d * dimw[j]);
#pragma unroll
    for (int o = 16; o; o >>= 1) lsum += __shfl_xor_sync(0xffffffffu, lsum, o);
    if (j == 0) dred[r] = lsum;
    __syncthreads();
    if (tid == 0) {
        double s = 0.0;
        for (int w = 0; w < 8; w++) s += dred[w];
        atomicAdd(&g_acc[0], s);
    }
}

__global__ void zero_acc() { g_acc[0] = 0.0; g_acc[1] = 0.0; }

__global__ void finalize_losses(float* __restrict__ lossOut) {
    double recon = g_acc[0] / (65536.0 * 32.0);
    double vq    = g_acc[1] / (65536.0 * 256.0);
    lossOut[0] = (float)recon;
    lossOut[1] = (float)vq;   // codebook_loss
    lossOut[2] = (float)vq;   // commit_loss (numerically identical)
}

extern "C" void kernel_launch(void* const* d_in, const int* in_sizes, int n_in,
                              void* d_out, int out_size) {
    const float* action = (const float*)d_in[0];
    const float* dimw   = (const float*)d_in[1];
    const float* ew0 = (const float*)d_in[2];
    const float* eb0 = (const float*)d_in[3];
    const float* ew1 = (const float*)d_in[4];
    const float* eb1 = (const float*)d_in[5];
    const float* ew2 = (const float*)d_in[6];
    const float* eb2 = (const float*)d_in[7];
    const float* dw0 = (const float*)d_in[8];
    const float* db0 = (const float*)d_in[9];
    const float* dw1 = (const float*)d_in[10];
    const float* db1 = (const float*)d_in[11];
    const float* dw2 = (const float*)d_in[12];
    const float* db2 = (const float*)d_in[13];
    const float* cb  = (const float*)d_in[14];
    float* out = (float*)d_out;

    void *pA, *pB, *pZE, *pCBN, *pD0, *pD1, *pD2;
    cudaGetSymbolAddress(&pA,   g_bufA);
    cudaGetSymbolAddress(&pB,   g_bufB);
    cudaGetSymbolAddress(&pZE,  g_ze);
    cudaGetSymbolAddress(&pCBN, g_cbn);
    cudaGetSymbolAddress(&pD0,  g_dt0);
    cudaGetSymbolAddress(&pD1,  g_dt1);
    cudaGetSymbolAddress(&pD2,  g_dt2);
    float* bufA = (float*)pA;
    float* bufB = (float*)pB;
    float* ze   = (float*)pZE;
    float* cbn  = (float*)pCBN;
    float* dt0  = (float*)pD0;
    float* dt1  = (float*)pD1;
    float* dt2  = (float*)pD2;

    // Output layout: action_hat [N*32], code_idx [N] (as float), 3 losses
    const size_t OFF_IDX  = (size_t)NTOK * ADIM;      // 2097152
    const size_t OFF_LOSS = OFF_IDX + NTOK;           // 2162688

    zero_acc<<<1, 1>>>();
    prep_cb<<<128, 256>>>(cb);
    // decoder table: MLP_dec over the 1024 normalized codebook rows
    sgemm_bias<true ><<<dim3(8, 8), 256>>>(cbn, dw0, db0, dt0, KCB, 1024, 256);
    sgemm_bias<true ><<<dim3(4, 8), 256>>>(dt0, dw1, db1, dt1, KCB, 512, 1024);
    dec2_table<<<128, 256>>>(dt1, dw2, db2, dt2);
    // encoder
    sgemm_bias<true ><<<dim3(4, 512), 256>>>(action, ew0, eb0, bufA, NTOK, 512, 32);
    sgemm_bias<true ><<<dim3(8, 512), 256>>>(bufA,   ew1, eb1, bufB, NTOK, 1024, 512);
    sgemm_bias<false><<<dim3(2, 512), 256>>>(bufB,   ew2, eb2, ze,   NTOK, 256, 1024);
    l2norm_rows<<<8192, 256>>>(ze, NTOK);
    // VQ: argmin + vq loss + code_idx output
    vq_kernel<<<512, 256>>>(ze, out + OFF_IDX);
    // gather decoder output per token + recon loss
    recon_gather<<<8192, 256>>>(dt2, out + OFF_IDX, action, dimw, out);
    finalize_losses<<<1, 1>>>(out + OFF_LOSS);
}

// round 4
// speedup vs baseline: 2.0797x; 1.0963x over previous
#include <cuda_runtime.h>
#include <math.h>

// Problem dims
#define NTOK 65536
#define ADIM 32
#define LDIM 256
#define KCB  1024

// Scratch (allocation-free: __device__ globals)
__device__ float  g_bufA[(size_t)NTOK * 1024];
__device__ float  g_bufB[(size_t)NTOK * 1024];
__device__ float  g_ze  [(size_t)NTOK * 256];
__device__ float  g_cbn [1024 * 256];
__device__ float  g_cbsq[1024];
__device__ float  g_dt0 [1024 * 1024];
__device__ float  g_dt1 [1024 * 512];
__device__ float  g_dt2 [1024 * 32];
__device__ double g_acc[2];   // [0]=recon sum, [1]=vq sum

typedef unsigned long long ull;

// ---------- packed f32x2 helpers (sm_100+) ----------
__device__ __forceinline__ ull f2pack(float lo, float hi) {
    ull r;
    asm("mov.b64 %0, {%1, %2};" : "=l"(r) : "f"(lo), "f"(hi));
    return r;
}
__device__ __forceinline__ void f2unpack(ull p, float& lo, float& hi) {
    asm("mov.b64 {%0, %1}, %2;" : "=f"(lo), "=f"(hi) : "l"(p));
}
__device__ __forceinline__ void fma2(ull& d, ull a, ull b) {
    asm("fma.rn.f32x2 %0, %1, %2, %0;" : "+l"(d) : "l"(a), "l"(b));
}

// jax.nn.gelu (approximate=True)
__device__ __forceinline__ float gelu_t(float x) {
    float x3 = x * x * x;
    float u  = 0.7978845608028654f * (x + 0.044715f * x3);
    return 0.5f * x * (1.0f + tanhf(u));
}

#define SPAD 132   // padded smem row (floats); 132*4B = 16B-aligned rows

// ---------- generic SGEMM: C = A[M,K] @ B[K,N] + bias, optional gelu ----------
// BM=BN=128, BK=16, 256 threads, split 4+4 microtile, f32x2 FMA,
// double-buffered smem with register prefetch. Requires M%128==0, N%128==0, K%16==0.
template<bool GELU>
__global__ __launch_bounds__(256, 2)
void sgemm_bias(const float* __restrict__ A, const float* __restrict__ B,
                const float* __restrict__ bias, float* __restrict__ C,
                int M, int N, int K) {
    __shared__ float As[2][16][SPAD];
    __shared__ float Bs[2][16][SPAD];
    const int tid   = threadIdx.x;
    const int tx    = tid & 15, ty = tid >> 4;
    const int aRow  = tid >> 2, aCol4 = (tid & 3) << 2;
    const int bRow  = tid >> 5, bCol4 = (tid & 31) << 2;
    const float* Ab = A + (size_t)blockIdx.y * 128 * K;
    const float* Bb = B + (size_t)blockIdx.x * 128;

    ull acc[8][4];
#pragma unroll
    for (int i = 0; i < 8; i++)
#pragma unroll
        for (int j = 0; j < 4; j++) acc[i][j] = 0ull;

    const int T = K >> 4;
    float4 pa0, pa1, pb0, pb1;

    pa0 = *(const float4*)(Ab + (size_t)aRow        * K + aCol4);
    pa1 = *(const float4*)(Ab + (size_t)(aRow + 64) * K + aCol4);
    pb0 = *(const float4*)(Bb + (size_t)bRow       * N + bCol4);
    pb1 = *(const float4*)(Bb + (size_t)(bRow + 8) * N + bCol4);
    {
        float* a0p = &As[0][aCol4][aRow];
        a0p[0 * SPAD] = pa0.x; a0p[1 * SPAD] = pa0.y; a0p[2 * SPAD] = pa0.z; a0p[3 * SPAD] = pa0.w;
        float* a1p = &As[0][aCol4][aRow + 64];
        a1p[0 * SPAD] = pa1.x; a1p[1 * SPAD] = pa1.y; a1p[2 * SPAD] = pa1.z; a1p[3 * SPAD] = pa1.w;
        *(float4*)(&Bs[0][bRow][bCol4])     = pb0;
        *(float4*)(&Bs[0][bRow + 8][bCol4]) = pb1;
    }
    __syncthreads();

    for (int t = 0; t < T; t++) {
        const int cur = t & 1;
        if (t + 1 < T) {
            const int k0 = (t + 1) << 4;
            pa0 = *(const float4*)(Ab + (size_t)aRow        * K + k0 + aCol4);
            pa1 = *(const float4*)(Ab + (size_t)(aRow + 64) * K + k0 + aCol4);
            pb0 = *(const float4*)(Bb + (size_t)(k0 + bRow)     * N + bCol4);
            pb1 = *(const float4*)(Bb + (size_t)(k0 + bRow + 8) * N + bCol4);
        }
#pragma unroll
        for (int k = 0; k < 16; k++) {
            float4 a0 = *(const float4*)(&As[cur][k][ty * 4]);
            float4 a1 = *(const float4*)(&As[cur][k][ty * 4 + 64]);
            ulonglong2 b01 = *(const ulonglong2*)(&Bs[cur][k][tx * 4]);
            ulonglong2 b23 = *(const ulonglong2*)(&Bs[cur][k][tx * 4 + 64]);
            ull bb2[4] = {b01.x, b01.y, b23.x, b23.y};
            float af[8] = {a0.x, a0.y, a0.z, a0.w, a1.x, a1.y, a1.z, a1.w};
#pragma unroll
            for (int i = 0; i < 8; i++) {
                ull a2 = f2pack(af[i], af[i]);
#pragma unroll
                for (int jp = 0; jp < 4; jp++) fma2(acc[i][jp], a2, bb2[jp]);
            }
        }
        if (t + 1 < T) {
            const int nxt = cur ^ 1;
            float* a0p = &As[nxt][aCol4][aRow];
            a0p[0 * SPAD] = pa0.x; a0p[1 * SPAD] = pa0.y; a0p[2 * SPAD] = pa0.z; a0p[3 * SPAD] = pa0.w;
            float* a1p = &As[nxt][aCol4][aRow + 64];
            a1p[0 * SPAD] = pa1.x; a1p[1 * SPAD] = pa1.y; a1p[2 * SPAD] = pa1.z; a1p[3 * SPAD] = pa1.w;
            *(float4*)(&Bs[nxt][bRow][bCol4])     = pb0;
            *(float4*)(&Bs[nxt][bRow + 8][bCol4]) = pb1;
        }
        __syncthreads();
    }

    const int row0 = blockIdx.y * 128;
    const int c0g  = blockIdx.x * 128 + tx * 4;
    float bl[4], bh[4];
#pragma unroll
    for (int j = 0; j < 4; j++) { bl[j] = bias[c0g + j]; bh[j] = bias[c0g + 64 + j]; }
#pragma unroll
    for (int i = 0; i < 8; i++) {
        const int row = row0 + ((i < 4) ? (ty * 4 + i) : (64 + ty * 4 + i - 4));
        float c[8];
#pragma unroll
        for (int jp = 0; jp < 4; jp++) f2unpack(acc[i][jp], c[jp * 2], c[jp * 2 + 1]);
#pragma unroll
        for (int j = 0; j < 4; j++) {
            float x0 = c[j]     + bl[j];
            float x1 = c[4 + j] + bh[j];
            if (GELU) { x0 = gelu_t(x0); x1 = gelu_t(x1); }
            c[j] = x0; c[4 + j] = x1;
        }
        float* Cp = C + (size_t)row * N + c0g;
        *(float4*)(Cp)      = make_float4(c[0], c[1], c[2], c[3]);
        *(float4*)(Cp + 64) = make_float4(c[4], c[5], c[6], c[7]);
    }
}

// ---------- small-tile SGEMM for the 1024-row table layers ----------
// BM=BN=64, BK=16, 128 threads, 4x8 microtile. High block count -> latency hidden.
template<bool GELU>
__global__ __launch_bounds__(128)
void sgemm64(const float* __restrict__ A, const float* __restrict__ B,
             const float* __restrict__ bias, float* __restrict__ C,
             int M, int N, int K) {
    __shared__ float As[16][68];
    __shared__ float Bs[16][68];
    const int tid  = threadIdx.x;
    const int tx   = tid & 7, ty = tid >> 3;       // tx: 8 col groups, ty: 16 row groups
    const int aRow = tid >> 1, aCol8 = (tid & 1) * 8;
    const int bRow = tid >> 3, bCol8 = (tid & 7) * 8;
    const float* Ab = A + (size_t)blockIdx.y * 64 * K;
    const float* Bb = B + (size_t)blockIdx.x * 64;

    ull acc[4][4];
#pragma unroll
    for (int i = 0; i < 4; i++)
#pragma unroll
        for (int j = 0; j < 4; j++) acc[i][j] = 0ull;

    for (int k0 = 0; k0 < K; k0 += 16) {
        float4 va0 = *(const float4*)(Ab + (size_t)aRow * K + k0 + aCol8);
        float4 va1 = *(const float4*)(Ab + (size_t)aRow * K + k0 + aCol8 + 4);
        float4 vb0 = *(const float4*)(Bb + (size_t)(k0 + bRow) * N + bCol8);
        float4 vb1 = *(const float4*)(Bb + (size_t)(k0 + bRow) * N + bCol8 + 4);
        __syncthreads();
        As[aCol8 + 0][aRow] = va0.x; As[aCol8 + 1][aRow] = va0.y;
        As[aCol8 + 2][aRow] = va0.z; As[aCol8 + 3][aRow] = va0.w;
        As[aCol8 + 4][aRow] = va1.x; As[aCol8 + 5][aRow] = va1.y;
        As[aCol8 + 6][aRow] = va1.z; As[aCol8 + 7][aRow] = va1.w;
        *(float4*)(&Bs[bRow][bCol8])     = vb0;
        *(float4*)(&Bs[bRow][bCol8 + 4]) = vb1;
        __syncthreads();
#pragma unroll
        for (int k = 0; k < 16; k++) {
            float4 a = *(const float4*)(&As[k][ty * 4]);
            ulonglong2 b01 = *(const ulonglong2*)(&Bs[k][tx * 4]);
            ulonglong2 b23 = *(const ulonglong2*)(&Bs[k][tx * 4 + 32]);
            ull bb2[4] = {b01.x, b01.y, b23.x, b23.y};
            float af[4] = {a.x, a.y, a.z, a.w};
#pragma unroll
            for (int i = 0; i < 4; i++) {
                ull a2 = f2pack(af[i], af[i]);
#pragma unroll
                for (int jp = 0; jp < 4; jp++) fma2(acc[i][jp], a2, bb2[jp]);
            }
        }
    }

    const int row0 = blockIdx.y * 64 + ty * 4;
    const int col0 = blockIdx.x * 64 + tx * 4;
    float bl[4], bh[4];
#pragma unroll
    for (int j = 0; j < 4; j++) { bl[j] = bias[col0 + j]; bh[j] = bias[col0 + 32 + j]; }
#pragma unroll
    for (int i = 0; i < 4; i++) {
        float c[8];
#pragma unroll
        for (int jp = 0; jp < 4; jp++) f2unpack(acc[i][jp], c[jp * 2], c[jp * 2 + 1]);
#pragma unroll
        for (int j = 0; j < 4; j++) {
            float x0 = c[j]     + bl[j];
            float x1 = c[4 + j] + bh[j];
            if (GELU) { x0 = gelu_t(x0); x1 = gelu_t(x1); }
            c[j] = x0; c[4 + j] = x1;
        }
        float* Cp = C + (size_t)(row0 + i) * N + col0;
        *(float4*)(Cp)      = make_float4(c[0], c[1], c[2], c[3]);
        *(float4*)(Cp + 32) = make_float4(c[4], c[5], c[6], c[7]);
    }
}

// ---------- codebook re-normalize + squared norms (one warp per row) ----------
__global__ void prep_cb(const float* __restrict__ cb) {
    int warp = (blockIdx.x * blockDim.x + threadIdx.x) >> 5;
    int lane = threadIdx.x & 31;
    if (warp >= 1024) return;
    const float* x = cb + (size_t)warp * 256;
    float v[8]; float s = 0.f;
#pragma unroll
    for (int i = 0; i < 8; i++) { v[i] = x[lane + i * 32]; s += v[i] * v[i]; }
#pragma unroll
    for (int o = 16; o; o >>= 1) s += __shfl_xor_sync(0xffffffffu, s, o);
    float den = sqrtf(s) + 1e-8f;
    float s2 = 0.f;
#pragma unroll
    for (int i = 0; i < 8; i++) {
        float y = v[i] / den;
        g_cbn[(size_t)warp * 256 + lane + i * 32] = y;
        s2 += y * y;
    }
#pragma unroll
    for (int o = 16; o; o >>= 1) s2 += __shfl_xor_sync(0xffffffffu, s2, o);
    if (lane == 0) g_cbsq[warp] = s2;
}

// ---------- fused distance-GEMM + argmin + VQ loss + recon gather/loss ----------
// One block per 128 UNNORMALIZED z_e rows. dist = cbsq - 2*alpha*dot (per-row
// alpha = 1/(||ze||+eps)); the row-constant ||zen||^2 is argmin-invariant and
// re-added analytically for the VQ loss. Packed (dist,idx) uint64 min gives
// exact first-min tie-break (matches jnp.argmin).
__global__ __launch_bounds__(256, 2)
void vq_kernel(const float* __restrict__ ZE, const float* __restrict__ tab,
               const float* __restrict__ action, const float* __restrict__ dimw,
               float* __restrict__ outAH, float* __restrict__ outIdxF) {
    __shared__ float As[2][16][SPAD];
    __shared__ float Bs[2][16][SPAD];
    __shared__ float scb[1024];
    __shared__ ull   bestp[128];
    __shared__ float salpha[128];
    __shared__ float snorm[128];
    __shared__ float sdimw[32];
    __shared__ double dred[8];
    __shared__ double rred[8];
    const int tid  = threadIdx.x;
    const int tx   = tid & 15, ty = tid >> 4;
    const int aRow = tid >> 2, aCol4 = (tid & 3) << 2;
    const float* Ab = ZE + (size_t)blockIdx.x * 128 * 256;

    for (int e = tid; e < 1024; e += 256) scb[e] = g_cbsq[e];
    if (tid < 32) sdimw[tid] = dimw[tid];
    if (tid < 128) bestp[tid] = ~0ull;

    // per-row alpha = 1/(||ze||+eps): 2 threads per row
    {
        const int row = tid >> 1, half = tid & 1;
        const float* rp = Ab + (size_t)row * 256 + half * 128;
        float s = 0.f;
#pragma unroll
        for (int i = 0; i < 32; i++) {
            float4 v = *(const float4*)(rp + i * 4);
            s += v.x * v.x + v.y * v.y + v.z * v.z + v.w * v.w;
        }
        s += __shfl_xor_sync(0xffffffffu, s, 1);
        if (half == 0) {
            snorm[row]  = s;
            salpha[row] = 1.0f / (sqrtf(s) + 1e-8f);
        }
    }

    for (int ct = 0; ct < 8; ct++) {
        const int cbase = ct * 128;
        const float* Bb = g_cbn + (size_t)cbase * 256;
        ull acc[8][4];
#pragma unroll
        for (int i = 0; i < 8; i++)
#pragma unroll
            for (int j = 0; j < 4; j++) acc[i][j] = 0ull;

        float4 pa0, pa1, pb0, pb1;
        pa0 = *(const float4*)(Ab + (size_t)aRow        * 256 + aCol4);
        pa1 = *(const float4*)(Ab + (size_t)(aRow + 64) * 256 + aCol4);
        pb0 = *(const float4*)(Bb + (size_t)aRow        * 256 + aCol4);
        pb1 = *(const float4*)(Bb + (size_t)(aRow + 64) * 256 + aCol4);
        __syncthreads();
        {   // tile 0 (both As and Bs stored transposed: [k][row/code])
            float* a0p = &As[0][aCol4][aRow];
            a0p[0 * SPAD] = pa0.x; a0p[1 * SPAD] = pa0.y; a0p[2 * SPAD] = pa0.z; a0p[3 * SPAD] = pa0.w;
            float* a1p = &As[0][aCol4][aRow + 64];
            a1p[0 * SPAD] = pa1.x; a1p[1 * SPAD] = pa1.y; a1p[2 * SPAD] = pa1.z; a1p[3 * SPAD] = pa1.w;
            float* b0p = &Bs[0][aCol4][aRow];
            b0p[0 * SPAD] = pb0.x; b0p[1 * SPAD] = pb0.y; b0p[2 * SPAD] = pb0.z; b0p[3 * SPAD] = pb0.w;
            float* b1p = &Bs[0][aCol4][aRow + 64];
            b1p[0 * SPAD] = pb1.x; b1p[1 * SPAD] = pb1.y; b1p[2 * SPAD] = pb1.z; b1p[3 * SPAD] = pb1.w;
        }
        __syncthreads();

        for (int t = 0; t < 16; t++) {
            const int cur = t & 1;
            if (t + 1 < 16) {
                const int k0 = (t + 1) << 4;
                pa0 = *(const float4*)(Ab + (size_t)aRow        * 256 + k0 + aCol4);
                pa1 = *(const float4*)(Ab + (size_t)(aRow + 64) * 256 + k0 + aCol4);
                pb0 = *(const float4*)(Bb + (size_t)aRow        * 256 + k0 + aCol4);
                pb1 = *(const float4*)(Bb + (size_t)(aRow + 64) * 256 + k0 + aCol4);
            }
#pragma unroll
            for (int k = 0; k < 16; k++) {
                float4 a0 = *(const float4*)(&As[cur][k][ty * 4]);
                float4 a1 = *(const float4*)(&As[cur][k][ty * 4 + 64]);
                ulonglong2 b01 = *(const ulonglong2*)(&Bs[cur][k][tx * 4]);
                ulonglong2 b23 = *(const ulonglong2*)(&Bs[cur][k][tx * 4 + 64]);
                ull bb2[4] = {b01.x, b01.y, b23.x, b23.y};
                float af[8] = {a0.x, a0.y, a0.z, a0.w, a1.x, a1.y, a1.z, a1.w};
#pragma unroll
                for (int i = 0; i < 8; i++) {
                    ull a2 = f2pack(af[i], af[i]);
#pragma unroll
                    for (int jp = 0; jp < 4; jp++) fma2(acc[i][jp], a2, bb2[jp]);
                }
            }
            if (t + 1 < 16) {
                const int nxt = cur ^ 1;
                float* a0p = &As[nxt][aCol4][aRow];
                a0p[0 * SPAD] = pa0.x; a0p[1 * SPAD] = pa0.y; a0p[2 * SPAD] = pa0.z; a0p[3 * SPAD] = pa0.w;
                float* a1p = &As[nxt][aCol4][aRow + 64];
                a1p[0 * SPAD] = pa1.x; a1p[1 * SPAD] = pa1.y; a1p[2 * SPAD] = pa1.z; a1p[3 * SPAD] = pa1.w;
                float* b0p = &Bs[nxt][aCol4][aRow];
                b0p[0 * SPAD] = pb0.x; b0p[1 * SPAD] = pb0.y; b0p[2 * SPAD] = pb0.z; b0p[3 * SPAD] = pb0.w;
                float* b1p = &Bs[nxt][aCol4][aRow + 64];
                b1p[0 * SPAD] = pb1.x; b1p[1 * SPAD] = pb1.y; b1p[2 * SPAD] = pb1.z; b1p[3 * SPAD] = pb1.w;
            }
            __syncthreads();
        }

        // per-thread packed mins over its 8 codes, half-warp reduce over tx
#pragma unroll
        for (int i = 0; i < 8; i++) {
            const int row = (i < 4) ? (ty * 4 + i) : (64 + ty * 4 + i - 4);
            const float m2a = -2.0f * salpha[row];
            ull pmin = ~0ull;
#pragma unroll
            for (int jp = 0; jp < 4; jp++) {
                float lo, hi; f2unpack(acc[i][jp], lo, hi);
                const int c0 = cbase + tx * 4 + ((jp >> 1) << 6) + ((jp & 1) << 1);
                float v0 = fmaf(m2a, lo, scb[c0]);
                float v1 = fmaf(m2a, hi, scb[c0 + 1]);
                ull p0 = ((ull)__float_as_uint(v0 + 8.f) << 32) | (unsigned)c0;
                ull p1 = ((ull)__float_as_uint(v1 + 8.f) << 32) | (unsigned)(c0 + 1);
                pmin = min(pmin, p0); pmin = min(pmin, p1);
            }
#pragma unroll
            for (int off = 8; off; off >>= 1) {
                ull o = __shfl_xor_sync(0xffffffffu, pmin, off);
                pmin = min(pmin, o);
            }
            if (tx == 0) bestp[row] = min(bestp[row], pmin);
        }
        __syncthreads();
    }

    // idx output + per-row vq loss: ||zen||^2 + (cbsq_idx - 2*alpha*dot_idx)
    double lsum = 0.0;
    if (tid < 128) {
        ull bp = bestp[tid];
        int besti = (int)(unsigned)(bp & 0xffffffffu);
        outIdxF[blockIdx.x * 128 + tid] = (float)besti;
        float bd = __uint_as_float((unsigned)(bp >> 32)) - 8.0f;
        float a  = salpha[tid];
        lsum = (double)(a * a * snorm[tid] + bd);
    }
#pragma unroll
    for (int o = 16; o; o >>= 1) lsum += __shfl_xor_sync(0xffffffffu, lsum, o);
    if ((tid & 31) == 0) dred[tid >> 5] = lsum;

    // recon: gather action_hat from table + weighted loss (one warp per token group)
    const int w = tid >> 5, lane = tid & 31;
    double rsum = 0.0;
    for (int rr = w; rr < 128; rr += 8) {
        int idx = (int)(unsigned)(bestp[rr] & 0xffffffffu);
        float ah = tab[(size_t)idx * 32 + lane];
        size_t gi = ((size_t)blockIdx.x * 128 + rr) * 32 + lane;
        outAH[gi] = ah;
        float d = action[gi] - ah;
        rsum += (double)(d * d * sdimw[lane]);
    }
#pragma unroll
    for (int o = 16; o; o >>= 1) rsum += __shfl_xor_sync(0xffffffffu, rsum, o);
    if (lane == 0) rred[w] = rsum;
    __syncthreads();
    if (tid == 0) {
        double t = 0.0, r = 0.0;
        for (int i = 0; i < 8; i++) { t += dred[i]; r += rred[i]; }
        atomicAdd(&g_acc[1], t);
        atomicAdd(&g_acc[0], r);
    }
}

// ---------- decoder final layer on the 1024-code table: [1024,512]@[512,32]+b ----------
__global__ __launch_bounds__(256)
void dec2_table(const float* __restrict__ X, const float* __restrict__ W,
                const float* __restrict__ b, float* __restrict__ outT) {
    __shared__ float xs[8][512];
    const int tid = threadIdx.x;
    const size_t rb = (size_t)blockIdx.x * 8;
    for (int e = tid; e < 8 * 512; e += 256)
        xs[e >> 9][e & 511] = X[rb * 512 + e];
    __syncthreads();
    const int r = tid >> 5, j = tid & 31;
    float a0 = 0.f, a1 = 0.f, a2 = 0.f, a3 = 0.f;
#pragma unroll 4
    for (int k = 0; k < 512; k += 4) {
        a0 = fmaf(xs[r][k + 0], W[(k + 0) * 32 + j], a0);
        a1 = fmaf(xs[r][k + 1], W[(k + 1) * 32 + j], a1);
        a2 = fmaf(xs[r][k + 2], W[(k + 2) * 32 + j], a2);
        a3 = fmaf(xs[r][k + 3], W[(k + 3) * 32 + j], a3);
    }
    outT[(rb + r) * 32 + j] = (a0 + a1) + (a2 + a3) + b[j];
}

__global__ void zero_acc() { g_acc[0] = 0.0; g_acc[1] = 0.0; }

__global__ void finalize_losses(float* __restrict__ lossOut) {
    double recon = g_acc[0] / (65536.0 * 32.0);
    double vq    = g_acc[1] / (65536.0 * 256.0);
    lossOut[0] = (float)recon;
    lossOut[1] = (float)vq;   // codebook_loss
    lossOut[2] = (float)vq;   // commit_loss (numerically identical)
}

extern "C" void kernel_launch(void* const* d_in, const int* in_sizes, int n_in,
                              void* d_out, int out_size) {
    const float* action = (const float*)d_in[0];
    const float* dimw   = (const float*)d_in[1];
    const float* ew0 = (const float*)d_in[2];
    const float* eb0 = (const float*)d_in[3];
    const float* ew1 = (const float*)d_in[4];
    const float* eb1 = (const float*)d_in[5];
    const float* ew2 = (const float*)d_in[6];
    const float* eb2 = (const float*)d_in[7];
    const float* dw0 = (const float*)d_in[8];
    const float* db0 = (const float*)d_in[9];
    const float* dw1 = (const float*)d_in[10];
    const float* db1 = (const float*)d_in[11];
    const float* dw2 = (const float*)d_in[12];
    const float* db2 = (const float*)d_in[13];
    const float* cb  = (const float*)d_in[14];
    float* out = (float*)d_out;

    void *pA, *pB, *pZE, *pCBN, *pD0, *pD1, *pD2;
    cudaGetSymbolAddress(&pA,   g_bufA);
    cudaGetSymbolAddress(&pB,   g_bufB);
    cudaGetSymbolAddress(&pZE,  g_ze);
    cudaGetSymbolAddress(&pCBN, g_cbn);
    cudaGetSymbolAddress(&pD0,  g_dt0);
    cudaGetSymbolAddress(&pD1,  g_dt1);
    cudaGetSymbolAddress(&pD2,  g_dt2);
    float* bufA = (float*)pA;
    float* bufB = (float*)pB;
    float* ze   = (float*)pZE;
    float* cbn  = (float*)pCBN;
    float* dt0  = (float*)pD0;
    float* dt1  = (float*)pD1;
    float* dt2  = (float*)pD2;

    // Output layout: action_hat [N*32], code_idx [N] (as float), 3 losses
    const size_t OFF_IDX  = (size_t)NTOK * ADIM;      // 2097152
    const size_t OFF_LOSS = OFF_IDX + NTOK;           // 2162688

    zero_acc<<<1, 1>>>();
    prep_cb<<<128, 256>>>(cb);
    // decoder table: MLP_dec over the 1024 normalized codebook rows (small tiles)
    sgemm64<true><<<dim3(16, 16), 128>>>(cbn, dw0, db0, dt0, KCB, 1024, 256);
    sgemm64<true><<<dim3(8, 16),  128>>>(dt0, dw1, db1, dt1, KCB, 512, 1024);
    dec2_table<<<128, 256>>>(dt1, dw2, db2, dt2);
    // encoder (ze left unnormalized; vq handles normalization analytically)
    sgemm_bias<true ><<<dim3(4, 512), 256>>>(action, ew0, eb0, bufA, NTOK, 512, 32);
    sgemm_bias<true ><<<dim3(8, 512), 256>>>(bufA,   ew1, eb1, bufB, NTOK, 1024, 512);
    sgemm_bias<false><<<dim3(2, 512), 256>>>(bufB,   ew2, eb2, ze,   NTOK, 256, 1024);
    // VQ: argmin + vq loss + idx + action_hat gather + recon loss, all fused
    vq_kernel<<<512, 256>>>(ze, dt2, action, dimw, out, out + OFF_IDX);
    finalize_losses<<<1, 1>>>(out + OFF_LOSS);
}